// round 10
// baseline (speedup 1.0000x reference)
#include <cuda_runtime.h>
#include <cstdint>
#include <math.h>

#define NB 8
#define SS 2048
#define DM 1024
#define NH 16
#define DH 64
#define MROWS (NB * SS)
#define ELEMS ((size_t)MROWS * DM)

__device__ float g_At[ELEMS];            // scaled+rounded A for GEMM3 only
__device__ float g_Q[ELEMS];             // Q = Q_seq @ WQ (fp32)
__device__ float g_QAK[ELEMS];           // QAK [b,h,s,dh]
__device__ float g_WT[DM * DM];          // transposed tf32 weight (reused 3x)
__device__ float g_logits[NB * NH * SS];
__device__ float g_qglob[NB * DM];
__device__ float g_kglob[NB * DM];
__device__ float g_WaT[NH * DM];
__device__ float g_WbT[NH * DM];

// ---------------- helpers ----------------
__device__ __forceinline__ uint32_t smem_u32(const void* p) {
    uint32_t a;
    asm("{ .reg .u64 t; cvta.to.shared.u64 t, %1; cvt.u32.u64 %0, t; }" : "=r"(a) : "l"(p));
    return a;
}
__device__ __forceinline__ void cp_async16(uint32_t s, const void* g) {
    asm volatile("cp.async.cg.shared.global [%0], [%1], 16;" :: "r"(s), "l"(g));
}
__device__ __forceinline__ void cp_commit() { asm volatile("cp.async.commit_group;" ::: "memory"); }
template <int N> __device__ __forceinline__ void cp_wait() {
    asm volatile("cp.async.wait_group %0;" :: "n"(N) : "memory");
}
__device__ __forceinline__ float rna_tf32(float x) {
    float r;
    asm("cvt.rna.tf32.f32 %0, %1;" : "=f"(r) : "f"(x));
    return r;
}
__device__ __forceinline__ void mma_tf32(float* c, const uint32_t* a, const uint32_t* b) {
    asm volatile(
        "mma.sync.aligned.m16n8k8.row.col.f32.tf32.tf32.f32 "
        "{%0,%1,%2,%3}, {%4,%5,%6,%7}, {%8,%9}, {%0,%1,%2,%3};"
        : "+f"(c[0]), "+f"(c[1]), "+f"(c[2]), "+f"(c[3])
        : "r"(a[0]), "r"(a[1]), "r"(a[2]), "r"(a[3]), "r"(b[0]), "r"(b[1]));
}

// ---------------- mma.sync tf32 GEMM ----------------
// C[M,N] = A[M,K] @ Bt[N,K]^T ; M=16384, N=1024, K=1024.
// BM=BN=128, BK=32, 256 threads, warp tile 32x64, 3-stage cp.async ring.
// ROUND_A: apply cvt.rna.tf32 to A fragments in-register (A is raw fp32).
#define BKF 32
#define ASTR 36
#define TILE_F (128 * ASTR)
#define STAGE_F (2 * TILE_F)
#define NST 3
#define KITERS (DM / BKF)
#define DYN_SMEM (NST * STAGE_F * 4)

// MODE 0: plain store. MODE 1: scale by aux[b,n], scatter to [b,h,s,dh]. MODE 2: + aux residual.
template <int MODE, int ROUND_A>
__global__ __launch_bounds__(256, 2) void gemm_mma(
    const float* __restrict__ A, const float* __restrict__ Bt,
    float* __restrict__ C, const float* __restrict__ aux)
{
    extern __shared__ float sm[];
    const uint32_t sbase = smem_u32(sm);
    const int tid = threadIdx.x;
    const int wid = tid >> 5, lane = tid & 31;
    const int warpM = wid & 3, warpN = wid >> 2;      // 4 x 2 warp grid
    const int grp = lane >> 2, qid = lane & 3;
    const int rowM = blockIdx.y * 128, rowN = blockIdx.x * 128;

    float acc[2][8][4];
#pragma unroll
    for (int i = 0; i < 2; i++)
#pragma unroll
        for (int j = 0; j < 8; j++)
#pragma unroll
            for (int l = 0; l < 4; l++) acc[i][j][l] = 0.0f;

    auto prefetch = [&](int kt, int slot) {
        const uint32_t sA = sbase + (uint32_t)slot * STAGE_F * 4;
        const uint32_t sB = sA + TILE_F * 4;
        const int kbase = kt * BKF;
#pragma unroll
        for (int j = 0; j < 4; j++) {
            const int t = tid + j * 256;
            const int row = t >> 3, g = t & 7;
            cp_async16(sA + (uint32_t)(row * ASTR + g * 4) * 4,
                       A + (size_t)(rowM + row) * DM + kbase + g * 4);
        }
#pragma unroll
        for (int j = 0; j < 4; j++) {
            const int t = tid + j * 256;
            const int row = t >> 3, g = t & 7;
            cp_async16(sB + (uint32_t)(row * ASTR + g * 4) * 4,
                       Bt + (size_t)(rowN + row) * DM + kbase + g * 4);
        }
        cp_commit();
    };

    prefetch(0, 0);
    prefetch(1, 1);

    for (int kt = 0; kt < KITERS; kt++) {
        if (kt < KITERS - 1) cp_wait<1>(); else cp_wait<0>();
        __syncthreads();
        if (kt + 2 < KITERS) prefetch(kt + 2, (kt + 2) % NST);

        const float* As = sm + (kt % NST) * STAGE_F;
        const float* Bs = As + TILE_F;
#pragma unroll
        for (int ks = 0; ks < 4; ks++) {
            const int c = ks * 8 + qid;
            uint32_t afr[2][4], bfr[8][2];
#pragma unroll
            for (int mt = 0; mt < 2; mt++) {
                const int r = warpM * 32 + mt * 16 + grp;
                float a0 = As[r * ASTR + c];
                float a1 = As[(r + 8) * ASTR + c];
                float a2 = As[r * ASTR + c + 4];
                float a3 = As[(r + 8) * ASTR + c + 4];
                if (ROUND_A) {
                    a0 = rna_tf32(a0); a1 = rna_tf32(a1);
                    a2 = rna_tf32(a2); a3 = rna_tf32(a3);
                }
                afr[mt][0] = __float_as_uint(a0);
                afr[mt][1] = __float_as_uint(a1);
                afr[mt][2] = __float_as_uint(a2);
                afr[mt][3] = __float_as_uint(a3);
            }
#pragma unroll
            for (int nt = 0; nt < 8; nt++) {
                const int n = warpN * 64 + nt * 8 + grp;
                bfr[nt][0] = __float_as_uint(Bs[n * ASTR + c]);
                bfr[nt][1] = __float_as_uint(Bs[n * ASTR + c + 4]);
            }
#pragma unroll
            for (int mt = 0; mt < 2; mt++)
#pragma unroll
                for (int nt = 0; nt < 8; nt++)
                    mma_tf32(acc[mt][nt], afr[mt], bfr[nt]);
        }
    }

    // Epilogue
    const int bB = rowM >> 11;
#pragma unroll
    for (int mt = 0; mt < 2; mt++) {
        const int r0 = rowM + warpM * 32 + mt * 16 + grp;
        const int r1 = r0 + 8;
        const int s0 = r0 & (SS - 1), s1 = r1 & (SS - 1);
#pragma unroll
        for (int nt = 0; nt < 8; nt++) {
            const int n = rowN + warpN * 64 + nt * 8 + qid * 2;
            const float* a4 = acc[mt][nt];
            if (MODE == 0) {
                *(float2*)(C + (size_t)r0 * DM + n) = make_float2(a4[0], a4[1]);
                *(float2*)(C + (size_t)r1 * DM + n) = make_float2(a4[2], a4[3]);
            } else if (MODE == 1) {
                const int h = n >> 6, d = n & 63;
                const float2 g = *(const float2*)(aux + (size_t)bB * DM + n);
                float* base = C + (((size_t)(bB * NH + h)) << 17) + d;  // *2048*64
                *(float2*)(base + (size_t)s0 * DH) = make_float2(a4[0] * g.x, a4[1] * g.y);
                *(float2*)(base + (size_t)s1 * DH) = make_float2(a4[2] * g.x, a4[3] * g.y);
            } else {
                const float2 q0 = *(const float2*)(aux + (size_t)r0 * DM + n);
                const float2 q1 = *(const float2*)(aux + (size_t)r1 * DM + n);
                *(float2*)(C + (size_t)r0 * DM + n) = make_float2(a4[0] + q0.x, a4[1] + q0.y);
                *(float2*)(C + (size_t)r1 * DM + n) = make_float2(a4[2] + q1.x, a4[3] + q1.y);
            }
        }
    }
}

// ---------------- conversion / small kernels ----------------
__global__ __launch_bounds__(256) void conv_scale_rna(
    const float4* __restrict__ Q, const float* __restrict__ kg,
    float4* __restrict__ out)
{
    const size_t i = (size_t)blockIdx.x * 256 + threadIdx.x;
    const int c4 = (int)(i & 255);
    const int b  = (int)(i >> 19);
    const float4 g = *(const float4*)(kg + (size_t)b * DM + c4 * 4);
    float4 v = Q[i];
    v.x = rna_tf32(v.x * g.x); v.y = rna_tf32(v.y * g.y);
    v.z = rna_tf32(v.z * g.z); v.w = rna_tf32(v.w * g.w);
    out[i] = v;
}

__global__ void transpose_rna(const float* __restrict__ W, float* __restrict__ WT)
{
    __shared__ float t[32][33];
    const int x0 = blockIdx.x * 32, y0 = blockIdx.y * 32;
    const int tx = threadIdx.x, ty = threadIdx.y;  // 32 x 8
#pragma unroll
    for (int j = 0; j < 32; j += 8)
        t[ty + j][tx] = W[(size_t)(y0 + ty + j) * DM + x0 + tx];
    __syncthreads();
#pragma unroll
    for (int j = 0; j < 32; j += 8)
        WT[(size_t)(x0 + ty + j) * DM + y0 + tx] = rna_tf32(t[tx][ty + j]);
}

__global__ void transpose_w(const float* __restrict__ W, float* __restrict__ WT)
{
    int i = blockIdx.x * 256 + threadIdx.x;
    if (i < DM * NH) {
        int j = i >> 4, e = i & 15;
        WT[e * DM + j] = W[i];
    }
}

// ---------------- row_logits: smem weights + 1024 blocks ----------------
#define LROWS 16
#define LOGIT_SMEM (NH * DM * 4)   // 65536
__global__ __launch_bounds__(256) void row_logits_sm(
    const float* __restrict__ rows, const float* __restrict__ WT,
    float* __restrict__ logits, float scaleF)
{
    extern __shared__ float4 w4[];   // [16 * 256] float4
    const int tid = threadIdx.x;
    const int wid = tid >> 5, lane = tid & 31;

    const float4* wt4 = (const float4*)WT;
#pragma unroll
    for (int i = 0; i < NH; i++)
        w4[i * 256 + tid] = wt4[i * 256 + tid];
    __syncthreads();

    const float4* w0 = w4 + (size_t)wid * 256;
    const float4* w1 = w4 + (size_t)(wid + 8) * 256;
    const int rbase = blockIdx.x * LROWS;

    for (int rr = 0; rr < LROWS; rr++) {
        const int r = rbase + rr;
        const float4* rp = (const float4*)(rows + (size_t)r * DM);
        float4 v[8];
#pragma unroll
        for (int j = 0; j < 8; j++) v[j] = rp[j * 32 + lane];

        float a0 = 0.0f, a1 = 0.0f;
#pragma unroll
        for (int j = 0; j < 8; j++) {
            const float4 u0 = w0[j * 32 + lane];
            const float4 u1 = w1[j * 32 + lane];
            a0 = fmaf(v[j].x, u0.x, a0); a0 = fmaf(v[j].y, u0.y, a0);
            a0 = fmaf(v[j].z, u0.z, a0); a0 = fmaf(v[j].w, u0.w, a0);
            a1 = fmaf(v[j].x, u1.x, a1); a1 = fmaf(v[j].y, u1.y, a1);
            a1 = fmaf(v[j].z, u1.z, a1); a1 = fmaf(v[j].w, u1.w, a1);
        }
#pragma unroll
        for (int o = 16; o; o >>= 1) {
            a0 += __shfl_xor_sync(0xffffffffu, a0, o);
            a1 += __shfl_xor_sync(0xffffffffu, a1, o);
        }
        if (lane == 0) {
            const int b = r >> 11, s = r & (SS - 1);
            logits[((size_t)(b * NH + wid)) * SS + s]     = a0 * scaleF;
            logits[((size_t)(b * NH + wid + 8)) * SS + s] = a1 * scaleF;
        }
    }
}

__global__ __launch_bounds__(256) void softmax_pool(
    const float* __restrict__ logits, const float* __restrict__ src,
    size_t bStride, size_t hStride, size_t sStride,
    float* __restrict__ out)
{
    const int bh = blockIdx.x;
    const int b = bh >> 4, h = bh & 15;
    const float* lg = logits + (size_t)bh * SS;

    __shared__ float w[SS];
    __shared__ float redm[8], reds[8];
    __shared__ float4 red4[16][16];
    __shared__ float s_max, s_inv;

    const int tid = threadIdx.x;
    const int warp = tid >> 5, lane = tid & 31;

    float m = -1e30f;
    for (int s = tid; s < SS; s += 256) m = fmaxf(m, lg[s]);
#pragma unroll
    for (int o = 16; o; o >>= 1) m = fmaxf(m, __shfl_xor_sync(0xffffffffu, m, o));
    if (lane == 0) redm[warp] = m;
    __syncthreads();
    if (tid == 0) {
        float mm = redm[0];
#pragma unroll
        for (int i = 1; i < 8; i++) mm = fmaxf(mm, redm[i]);
        s_max = mm;
    }
    __syncthreads();
    const float mx = s_max;

    float sum = 0.0f;
    for (int s = tid; s < SS; s += 256) {
        const float e = __expf(lg[s] - mx);
        w[s] = e;
        sum += e;
    }
#pragma unroll
    for (int o = 16; o; o >>= 1) sum += __shfl_xor_sync(0xffffffffu, sum, o);
    if (lane == 0) reds[warp] = sum;
    __syncthreads();
    if (tid == 0) {
        float ss = 0.0f;
#pragma unroll
        for (int i = 0; i < 8; i++) ss += reds[i];
        s_inv = 1.0f / ss;
    }
    __syncthreads();
    const float inv = s_inv;

    const int d4 = tid & 15, sg = tid >> 4;
    const float* sp = src + (size_t)b * bStride + (size_t)h * hStride + d4 * 4;
    float4 acc = make_float4(0.f, 0.f, 0.f, 0.f);
    for (int s = sg; s < SS; s += 16) {
        const float4 v = *(const float4*)(sp + (size_t)s * sStride);
        const float ws = w[s];
        acc.x = fmaf(ws, v.x, acc.x); acc.y = fmaf(ws, v.y, acc.y);
        acc.z = fmaf(ws, v.z, acc.z); acc.w = fmaf(ws, v.w, acc.w);
    }
    red4[sg][d4] = acc;
    __syncthreads();
    if (sg == 0) {
        float4 t = red4[0][d4];
#pragma unroll
        for (int g = 1; g < 16; g++) {
            const float4 u = red4[g][d4];
            t.x += u.x; t.y += u.y; t.z += u.z; t.w += u.w;
        }
        *(float4*)(out + (size_t)bh * DH + d4 * 4) =
            make_float4(t.x * inv, t.y * inv, t.z * inv, t.w * inv);
    }
}

// ---------------------------------------------------------------------------
extern "C" void kernel_launch(void* const* d_in, const int* in_sizes, int n_in,
                              void* d_out, int out_size)
{
    const float* Q_seq = (const float*)d_in[0];
    const float* K_seq = (const float*)d_in[1];
    const float* WQ = (const float*)d_in[3];
    const float* WK = (const float*)d_in[4];
    const float* Wa = (const float*)d_in[5];
    const float* Wb = (const float*)d_in[6];
    const float* WP = (const float*)d_in[7];
    float* out = (float*)d_out;

    float *pAt, *pQ, *pQAK, *pWT, *pLg, *pQg, *pKg, *pWaT, *pWbT;
    cudaGetSymbolAddress((void**)&pAt,  g_At);
    cudaGetSymbolAddress((void**)&pQ,   g_Q);
    cudaGetSymbolAddress((void**)&pQAK, g_QAK);
    cudaGetSymbolAddress((void**)&pWT,  g_WT);
    cudaGetSymbolAddress((void**)&pLg,  g_logits);
    cudaGetSymbolAddress((void**)&pQg,  g_qglob);
    cudaGetSymbolAddress((void**)&pKg,  g_kglob);
    cudaGetSymbolAddress((void**)&pWaT, g_WaT);
    cudaGetSymbolAddress((void**)&pWbT, g_WbT);

    cudaFuncSetAttribute((const void*)gemm_mma<0,1>, cudaFuncAttributeMaxDynamicSharedMemorySize, DYN_SMEM);
    cudaFuncSetAttribute((const void*)gemm_mma<1,1>, cudaFuncAttributeMaxDynamicSharedMemorySize, DYN_SMEM);
    cudaFuncSetAttribute((const void*)gemm_mma<2,0>, cudaFuncAttributeMaxDynamicSharedMemorySize, DYN_SMEM);
    cudaFuncSetAttribute(row_logits_sm, cudaFuncAttributeMaxDynamicSharedMemorySize, LOGIT_SMEM);

    const float scaleF = 0.125f;
    const dim3 ggrid(DM / 128, MROWS / 128);     // (8, 128)
    const dim3 tgrid(32, 32), tblk(32, 8);
    const unsigned cgrid = (unsigned)(ELEMS / 4 / 256);

    transpose_w<<<(DM * NH + 255) / 256, 256>>>(Wa, pWaT);
    transpose_w<<<(DM * NH + 255) / 256, 256>>>(Wb, pWbT);

    // 1. Q = Q_seq @ WQ  (A rounded in-register, read directly from input)
    transpose_rna<<<tgrid, tblk>>>(WQ, pWT);
    gemm_mma<0,1><<<ggrid, 256, DYN_SMEM>>>(Q_seq, pWT, pQ, nullptr);

    // 2. alpha = softmax(Q @ Wa * scale); q_glob = pool(alpha, Qh)
    row_logits_sm<<<MROWS / LROWS, 256, LOGIT_SMEM>>>(pQ, pWaT, pLg, scaleF);
    softmax_pool<<<NB * NH, 256>>>(pLg, pQ,
                                   (size_t)SS * DM, (size_t)DH, (size_t)DM, pQg);

    // 3. QAK = (K_seq @ WK) * q_glob, scattered to [b,h,s,dh]
    transpose_rna<<<tgrid, tblk>>>(WK, pWT);
    gemm_mma<1,1><<<ggrid, 256, DYN_SMEM>>>(K_seq, pWT, pQAK, pQg);

    // 4. beta = softmax(QAK_D @ Wb * scale); k_glob = pool(beta, QAK)
    row_logits_sm<<<MROWS / LROWS, 256, LOGIT_SMEM>>>(pQAK, pWbT, pLg, scaleF);
    softmax_pool<<<NB * NH, 256>>>(pLg, pQAK,
                                   (size_t)NH * SS * DH, (size_t)SS * DH, (size_t)DH, pKg);

    // 5. out = (Q * k_glob) @ WP + Q
    conv_scale_rna<<<cgrid, 256>>>((const float4*)pQ, pKg, (float4*)pAt);
    transpose_rna<<<tgrid, tblk>>>(WP, pWT);
    gemm_mma<2,0><<<ggrid, 256, DYN_SMEM>>>(pAt, pWT, out, pQ);
}

// round 11
// speedup vs baseline: 1.5054x; 1.5054x over previous
#include <cuda_runtime.h>
#include <cstdint>
#include <math.h>

#define NB 8
#define SS 2048
#define DM 1024
#define NH 16
#define DH 64
#define MROWS (NB * SS)
#define ELEMS ((size_t)MROWS * DM)

__device__ float g_At[ELEMS];            // scaled+rounded A for GEMM3 only
__device__ float g_Q[ELEMS];             // Q = Q_seq @ WQ (fp32)
__device__ float g_QAK[ELEMS];           // QAK [b,h,s,dh]
__device__ float g_WT[DM * DM];          // transposed tf32 weight (reused 3x)
__device__ float g_logits[NB * NH * SS];
__device__ float g_qglob[NB * DM];
__device__ float g_kglob[NB * DM];
__device__ float g_WaT[NH * DM];
__device__ float g_WbT[NH * DM];

// ---------------- helpers ----------------
__device__ __forceinline__ uint32_t smem_u32(const void* p) {
    uint32_t a;
    asm("{ .reg .u64 t; cvta.to.shared.u64 t, %1; cvt.u32.u64 %0, t; }" : "=r"(a) : "l"(p));
    return a;
}
__device__ __forceinline__ void cp_async16(uint32_t s, const void* g) {
    asm volatile("cp.async.cg.shared.global [%0], [%1], 16;" :: "r"(s), "l"(g));
}
__device__ __forceinline__ void cp_commit() { asm volatile("cp.async.commit_group;" ::: "memory"); }
template <int N> __device__ __forceinline__ void cp_wait() {
    asm volatile("cp.async.wait_group %0;" :: "n"(N) : "memory");
}
__device__ __forceinline__ float rna_tf32(float x) {
    float r;
    asm("cvt.rna.tf32.f32 %0, %1;" : "=f"(r) : "f"(x));
    return r;
}
__device__ __forceinline__ void mma_tf32(float* c, const uint32_t* a, const uint32_t* b) {
    asm volatile(
        "mma.sync.aligned.m16n8k8.row.col.f32.tf32.tf32.f32 "
        "{%0,%1,%2,%3}, {%4,%5,%6,%7}, {%8,%9}, {%0,%1,%2,%3};"
        : "+f"(c[0]), "+f"(c[1]), "+f"(c[2]), "+f"(c[3])
        : "r"(a[0]), "r"(a[1]), "r"(a[2]), "r"(a[3]), "r"(b[0]), "r"(b[1]));
}

// ---------------- mma.sync tf32 GEMM (R4 version, verbatim) ----------------
// C[M,N] = A[M,K] @ Bt[N,K]^T ; M=16384, N=1024, K=1024.
// BM=BN=128, BK=32, 256 threads, warp tile 32x64, 3-stage cp.async ring.
// A may be raw fp32 (HW truncates to tf32); B must be pre-rounded.
#define BKF 32
#define ASTR 36
#define TILE_F (128 * ASTR)
#define STAGE_F (2 * TILE_F)
#define NST 3
#define KITERS (DM / BKF)
#define DYN_SMEM (NST * STAGE_F * 4)

// MODE 0: plain store. MODE 1: scale by aux[b,n], scatter to [b,h,s,dh]. MODE 2: + aux residual.
template <int MODE>
__global__ __launch_bounds__(256, 2) void gemm_mma(
    const float* __restrict__ A, const float* __restrict__ Bt,
    float* __restrict__ C, const float* __restrict__ aux)
{
    extern __shared__ float sm[];
    const uint32_t sbase = smem_u32(sm);
    const int tid = threadIdx.x;
    const int wid = tid >> 5, lane = tid & 31;
    const int warpM = wid & 3, warpN = wid >> 2;      // 4 x 2 warp grid
    const int grp = lane >> 2, qid = lane & 3;
    const int rowM = blockIdx.y * 128, rowN = blockIdx.x * 128;

    float acc[2][8][4];
#pragma unroll
    for (int i = 0; i < 2; i++)
#pragma unroll
        for (int j = 0; j < 8; j++)
#pragma unroll
            for (int l = 0; l < 4; l++) acc[i][j][l] = 0.0f;

    auto prefetch = [&](int kt, int slot) {
        const uint32_t sA = sbase + (uint32_t)slot * STAGE_F * 4;
        const uint32_t sB = sA + TILE_F * 4;
        const int kbase = kt * BKF;
#pragma unroll
        for (int j = 0; j < 4; j++) {
            const int t = tid + j * 256;
            const int row = t >> 3, g = t & 7;
            cp_async16(sA + (uint32_t)(row * ASTR + g * 4) * 4,
                       A + (size_t)(rowM + row) * DM + kbase + g * 4);
        }
#pragma unroll
        for (int j = 0; j < 4; j++) {
            const int t = tid + j * 256;
            const int row = t >> 3, g = t & 7;
            cp_async16(sB + (uint32_t)(row * ASTR + g * 4) * 4,
                       Bt + (size_t)(rowN + row) * DM + kbase + g * 4);
        }
        cp_commit();
    };

    prefetch(0, 0);
    prefetch(1, 1);

    for (int kt = 0; kt < KITERS; kt++) {
        if (kt < KITERS - 1) cp_wait<1>(); else cp_wait<0>();
        __syncthreads();
        if (kt + 2 < KITERS) prefetch(kt + 2, (kt + 2) % NST);

        const float* As = sm + (kt % NST) * STAGE_F;
        const float* Bs = As + TILE_F;
#pragma unroll
        for (int ks = 0; ks < 4; ks++) {
            const int c = ks * 8 + qid;
            uint32_t afr[2][4], bfr[8][2];
#pragma unroll
            for (int mt = 0; mt < 2; mt++) {
                const int r = warpM * 32 + mt * 16 + grp;
                afr[mt][0] = __float_as_uint(As[r * ASTR + c]);
                afr[mt][1] = __float_as_uint(As[(r + 8) * ASTR + c]);
                afr[mt][2] = __float_as_uint(As[r * ASTR + c + 4]);
                afr[mt][3] = __float_as_uint(As[(r + 8) * ASTR + c + 4]);
            }
#pragma unroll
            for (int nt = 0; nt < 8; nt++) {
                const int n = warpN * 64 + nt * 8 + grp;
                bfr[nt][0] = __float_as_uint(Bs[n * ASTR + c]);
                bfr[nt][1] = __float_as_uint(Bs[n * ASTR + c + 4]);
            }
#pragma unroll
            for (int mt = 0; mt < 2; mt++)
#pragma unroll
                for (int nt = 0; nt < 8; nt++)
                    mma_tf32(acc[mt][nt], afr[mt], bfr[nt]);
        }
    }

    // Epilogue
    const int bB = rowM >> 11;
#pragma unroll
    for (int mt = 0; mt < 2; mt++) {
        const int r0 = rowM + warpM * 32 + mt * 16 + grp;
        const int r1 = r0 + 8;
        const int s0 = r0 & (SS - 1), s1 = r1 & (SS - 1);
#pragma unroll
        for (int nt = 0; nt < 8; nt++) {
            const int n = rowN + warpN * 64 + nt * 8 + qid * 2;
            const float* a4 = acc[mt][nt];
            if (MODE == 0) {
                *(float2*)(C + (size_t)r0 * DM + n) = make_float2(a4[0], a4[1]);
                *(float2*)(C + (size_t)r1 * DM + n) = make_float2(a4[2], a4[3]);
            } else if (MODE == 1) {
                const int h = n >> 6, d = n & 63;
                const float2 g = *(const float2*)(aux + (size_t)bB * DM + n);
                float* base = C + (((size_t)(bB * NH + h)) << 17) + d;  // *2048*64
                *(float2*)(base + (size_t)s0 * DH) = make_float2(a4[0] * g.x, a4[1] * g.y);
                *(float2*)(base + (size_t)s1 * DH) = make_float2(a4[2] * g.x, a4[3] * g.y);
            } else {
                const float2 q0 = *(const float2*)(aux + (size_t)r0 * DM + n);
                const float2 q1 = *(const float2*)(aux + (size_t)r1 * DM + n);
                *(float2*)(C + (size_t)r0 * DM + n) = make_float2(a4[0] + q0.x, a4[1] + q0.y);
                *(float2*)(C + (size_t)r1 * DM + n) = make_float2(a4[2] + q1.x, a4[3] + q1.y);
            }
        }
    }
}

// ---------------- conversion / small kernels ----------------
__global__ __launch_bounds__(256) void conv_scale_rna(
    const float4* __restrict__ Q, const float* __restrict__ kg,
    float4* __restrict__ out)
{
    const size_t i = (size_t)blockIdx.x * 256 + threadIdx.x;
    const int c4 = (int)(i & 255);
    const int b  = (int)(i >> 19);
    const float4 g = *(const float4*)(kg + (size_t)b * DM + c4 * 4);
    float4 v = Q[i];
    v.x = rna_tf32(v.x * g.x); v.y = rna_tf32(v.y * g.y);
    v.z = rna_tf32(v.z * g.z); v.w = rna_tf32(v.w * g.w);
    out[i] = v;
}

__global__ void transpose_rna(const float* __restrict__ W, float* __restrict__ WT)
{
    __shared__ float t[32][33];
    const int x0 = blockIdx.x * 32, y0 = blockIdx.y * 32;
    const int tx = threadIdx.x, ty = threadIdx.y;  // 32 x 8
#pragma unroll
    for (int j = 0; j < 32; j += 8)
        t[ty + j][tx] = W[(size_t)(y0 + ty + j) * DM + x0 + tx];
    __syncthreads();
#pragma unroll
    for (int j = 0; j < 32; j += 8)
        WT[(size_t)(x0 + ty + j) * DM + y0 + tx] = rna_tf32(t[tx][ty + j]);
}

__global__ void transpose_w(const float* __restrict__ W, float* __restrict__ WT)
{
    int i = blockIdx.x * 256 + threadIdx.x;
    if (i < DM * NH) {
        int j = i >> 4, e = i & 15;
        WT[e * DM + j] = W[i];
    }
}

// ---------------- row_logits: smem weights + 1024 blocks ----------------
#define LROWS 16
#define LOGIT_SMEM (NH * DM * 4)   // 65536
__global__ __launch_bounds__(256) void row_logits_sm(
    const float* __restrict__ rows, const float* __restrict__ WT,
    float* __restrict__ logits, float scaleF)
{
    extern __shared__ float4 w4[];   // [16 * 256] float4
    const int tid = threadIdx.x;
    const int wid = tid >> 5, lane = tid & 31;

    const float4* wt4 = (const float4*)WT;
#pragma unroll
    for (int i = 0; i < NH; i++)
        w4[i * 256 + tid] = wt4[i * 256 + tid];
    __syncthreads();

    const float4* w0 = w4 + (size_t)wid * 256;
    const float4* w1 = w4 + (size_t)(wid + 8) * 256;
    const int rbase = blockIdx.x * LROWS;

    for (int rr = 0; rr < LROWS; rr++) {
        const int r = rbase + rr;
        const float4* rp = (const float4*)(rows + (size_t)r * DM);
        float4 v[8];
#pragma unroll
        for (int j = 0; j < 8; j++) v[j] = rp[j * 32 + lane];

        float a0 = 0.0f, a1 = 0.0f;
#pragma unroll
        for (int j = 0; j < 8; j++) {
            const float4 u0 = w0[j * 32 + lane];
            const float4 u1 = w1[j * 32 + lane];
            a0 = fmaf(v[j].x, u0.x, a0); a0 = fmaf(v[j].y, u0.y, a0);
            a0 = fmaf(v[j].z, u0.z, a0); a0 = fmaf(v[j].w, u0.w, a0);
            a1 = fmaf(v[j].x, u1.x, a1); a1 = fmaf(v[j].y, u1.y, a1);
            a1 = fmaf(v[j].z, u1.z, a1); a1 = fmaf(v[j].w, u1.w, a1);
        }
#pragma unroll
        for (int o = 16; o; o >>= 1) {
            a0 += __shfl_xor_sync(0xffffffffu, a0, o);
            a1 += __shfl_xor_sync(0xffffffffu, a1, o);
        }
        if (lane == 0) {
            const int b = r >> 11, s = r & (SS - 1);
            logits[((size_t)(b * NH + wid)) * SS + s]     = a0 * scaleF;
            logits[((size_t)(b * NH + wid + 8)) * SS + s] = a1 * scaleF;
        }
    }
}

__global__ __launch_bounds__(256) void softmax_pool(
    const float* __restrict__ logits, const float* __restrict__ src,
    size_t bStride, size_t hStride, size_t sStride,
    float* __restrict__ out)
{
    const int bh = blockIdx.x;
    const int b = bh >> 4, h = bh & 15;
    const float* lg = logits + (size_t)bh * SS;

    __shared__ float w[SS];
    __shared__ float redm[8], reds[8];
    __shared__ float4 red4[16][16];
    __shared__ float s_max, s_inv;

    const int tid = threadIdx.x;
    const int warp = tid >> 5, lane = tid & 31;

    float m = -1e30f;
    for (int s = tid; s < SS; s += 256) m = fmaxf(m, lg[s]);
#pragma unroll
    for (int o = 16; o; o >>= 1) m = fmaxf(m, __shfl_xor_sync(0xffffffffu, m, o));
    if (lane == 0) redm[warp] = m;
    __syncthreads();
    if (tid == 0) {
        float mm = redm[0];
#pragma unroll
        for (int i = 1; i < 8; i++) mm = fmaxf(mm, redm[i]);
        s_max = mm;
    }
    __syncthreads();
    const float mx = s_max;

    float sum = 0.0f;
    for (int s = tid; s < SS; s += 256) {
        const float e = __expf(lg[s] - mx);
        w[s] = e;
        sum += e;
    }
#pragma unroll
    for (int o = 16; o; o >>= 1) sum += __shfl_xor_sync(0xffffffffu, sum, o);
    if (lane == 0) reds[warp] = sum;
    __syncthreads();
    if (tid == 0) {
        float ss = 0.0f;
#pragma unroll
        for (int i = 0; i < 8; i++) ss += reds[i];
        s_inv = 1.0f / ss;
    }
    __syncthreads();
    const float inv = s_inv;

    const int d4 = tid & 15, sg = tid >> 4;
    const float* sp = src + (size_t)b * bStride + (size_t)h * hStride + d4 * 4;
    float4 acc = make_float4(0.f, 0.f, 0.f, 0.f);
    for (int s = sg; s < SS; s += 16) {
        const float4 v = *(const float4*)(sp + (size_t)s * sStride);
        const float ws = w[s];
        acc.x = fmaf(ws, v.x, acc.x); acc.y = fmaf(ws, v.y, acc.y);
        acc.z = fmaf(ws, v.z, acc.z); acc.w = fmaf(ws, v.w, acc.w);
    }
    red4[sg][d4] = acc;
    __syncthreads();
    if (sg == 0) {
        float4 t = red4[0][d4];
#pragma unroll
        for (int g = 1; g < 16; g++) {
            const float4 u = red4[g][d4];
            t.x += u.x; t.y += u.y; t.z += u.z; t.w += u.w;
        }
        *(float4*)(out + (size_t)bh * DH + d4 * 4) =
            make_float4(t.x * inv, t.y * inv, t.z * inv, t.w * inv);
    }
}

// ---------------------------------------------------------------------------
extern "C" void kernel_launch(void* const* d_in, const int* in_sizes, int n_in,
                              void* d_out, int out_size)
{
    const float* Q_seq = (const float*)d_in[0];
    const float* K_seq = (const float*)d_in[1];
    const float* WQ = (const float*)d_in[3];
    const float* WK = (const float*)d_in[4];
    const float* Wa = (const float*)d_in[5];
    const float* Wb = (const float*)d_in[6];
    const float* WP = (const float*)d_in[7];
    float* out = (float*)d_out;

    float *pAt, *pQ, *pQAK, *pWT, *pLg, *pQg, *pKg, *pWaT, *pWbT;
    cudaGetSymbolAddress((void**)&pAt,  g_At);
    cudaGetSymbolAddress((void**)&pQ,   g_Q);
    cudaGetSymbolAddress((void**)&pQAK, g_QAK);
    cudaGetSymbolAddress((void**)&pWT,  g_WT);
    cudaGetSymbolAddress((void**)&pLg,  g_logits);
    cudaGetSymbolAddress((void**)&pQg,  g_qglob);
    cudaGetSymbolAddress((void**)&pKg,  g_kglob);
    cudaGetSymbolAddress((void**)&pWaT, g_WaT);
    cudaGetSymbolAddress((void**)&pWbT, g_WbT);

    cudaFuncSetAttribute(gemm_mma<0>, cudaFuncAttributeMaxDynamicSharedMemorySize, DYN_SMEM);
    cudaFuncSetAttribute(gemm_mma<1>, cudaFuncAttributeMaxDynamicSharedMemorySize, DYN_SMEM);
    cudaFuncSetAttribute(gemm_mma<2>, cudaFuncAttributeMaxDynamicSharedMemorySize, DYN_SMEM);
    cudaFuncSetAttribute(row_logits_sm, cudaFuncAttributeMaxDynamicSharedMemorySize, LOGIT_SMEM);

    const float scaleF = 0.125f;
    const dim3 ggrid(DM / 128, MROWS / 128);     // (8, 128)
    const dim3 tgrid(32, 32), tblk(32, 8);
    const unsigned cgrid = (unsigned)(ELEMS / 4 / 256);

    transpose_w<<<(DM * NH + 255) / 256, 256>>>(Wa, pWaT);
    transpose_w<<<(DM * NH + 255) / 256, 256>>>(Wb, pWbT);

    // 1. Q = Q_seq @ WQ  (A raw fp32 -> HW tf32 truncation; B RNA-rounded)
    transpose_rna<<<tgrid, tblk>>>(WQ, pWT);
    gemm_mma<0><<<ggrid, 256, DYN_SMEM>>>(Q_seq, pWT, pQ, nullptr);

    // 2. alpha = softmax(Q @ Wa * scale); q_glob = pool(alpha, Qh)
    row_logits_sm<<<MROWS / LROWS, 256, LOGIT_SMEM>>>(pQ, pWaT, pLg, scaleF);
    softmax_pool<<<NB * NH, 256>>>(pLg, pQ,
                                   (size_t)SS * DM, (size_t)DH, (size_t)DM, pQg);

    // 3. QAK = (K_seq @ WK) * q_glob, scattered to [b,h,s,dh]
    transpose_rna<<<tgrid, tblk>>>(WK, pWT);
    gemm_mma<1><<<ggrid, 256, DYN_SMEM>>>(K_seq, pWT, pQAK, pQg);

    // 4. beta = softmax(QAK_D @ Wb * scale); k_glob = pool(beta, QAK)
    row_logits_sm<<<MROWS / LROWS, 256, LOGIT_SMEM>>>(pQAK, pWbT, pLg, scaleF);
    softmax_pool<<<NB * NH, 256>>>(pLg, pQAK,
                                   (size_t)NH * SS * DH, (size_t)SS * DH, (size_t)DH, pKg);

    // 5. out = (Q * k_glob) @ WP + Q  (A scaled+RNA-rounded by conv kernel)
    conv_scale_rna<<<cgrid, 256>>>((const float4*)pQ, pKg, (float4*)pAt);
    transpose_rna<<<tgrid, tblk>>>(WP, pWT);
    gemm_mma<2><<<ggrid, 256, DYN_SMEM>>>(pAt, pWT, out, pQ);
}

// round 12
// speedup vs baseline: 1.5527x; 1.0314x over previous
#include <cuda_runtime.h>
#include <cstdint>
#include <math.h>

#define NB 8
#define SS 2048
#define DM 1024
#define NH 16
#define DH 64
#define MROWS (NB * SS)
#define ELEMS ((size_t)MROWS * DM)

__device__ float g_At[ELEMS];            // scaled+rounded A for GEMM3 only
__device__ float g_Q[ELEMS];             // Q = Q_seq @ WQ (fp32)
__device__ float g_QAK[ELEMS];           // QAK [b,h,s,dh]
__device__ float g_WT[DM * DM];          // transposed tf32 weight (reused 3x)
__device__ float g_logits[NB * NH * SS];
__device__ float g_qglob[NB * DM];
__device__ float g_kglob[NB * DM];
__device__ float g_WaT[NH * DM];
__device__ float g_WbT[NH * DM];

// ---------------- helpers ----------------
__device__ __forceinline__ uint32_t smem_u32(const void* p) {
    uint32_t a;
    asm("{ .reg .u64 t; cvta.to.shared.u64 t, %1; cvt.u32.u64 %0, t; }" : "=r"(a) : "l"(p));
    return a;
}
__device__ __forceinline__ void cp_async16(uint32_t s, const void* g) {
    asm volatile("cp.async.cg.shared.global [%0], [%1], 16;" :: "r"(s), "l"(g));
}
__device__ __forceinline__ void cp_commit() { asm volatile("cp.async.commit_group;" ::: "memory"); }
template <int N> __device__ __forceinline__ void cp_wait() {
    asm volatile("cp.async.wait_group %0;" :: "n"(N) : "memory");
}
__device__ __forceinline__ float rna_tf32(float x) {
    float r;
    asm("cvt.rna.tf32.f32 %0, %1;" : "=f"(r) : "f"(x));
    return r;
}
__device__ __forceinline__ void mma_tf32(float* c, const uint32_t* a, const uint32_t* b) {
    asm volatile(
        "mma.sync.aligned.m16n8k8.row.col.f32.tf32.tf32.f32 "
        "{%0,%1,%2,%3}, {%4,%5,%6,%7}, {%8,%9}, {%0,%1,%2,%3};"
        : "+f"(c[0]), "+f"(c[1]), "+f"(c[2]), "+f"(c[3])
        : "r"(a[0]), "r"(a[1]), "r"(a[2]), "r"(a[3]), "r"(b[0]), "r"(b[1]));
}

// ---------------- mma.sync tf32 GEMM: 128 threads, warp tile 64x64 ----------------
// C[M,N] = A[M,K] @ Bt[N,K]^T ; M=16384, N=1024, K=1024.
// BM=BN=128, BK=32, 4 warps (2x2), 3-stage cp.async ring, 2 CTAs/SM.
// A may be raw fp32 (HW truncates to tf32); B must be pre-rounded.
#define BKF 32
#define ASTR 36
#define TILE_F (128 * ASTR)
#define STAGE_F (2 * TILE_F)
#define NST 3
#define KITERS (DM / BKF)
#define DYN_SMEM (NST * STAGE_F * 4)

// MODE 0: plain store. MODE 1: scale by aux[b,n], scatter to [b,h,s,dh]. MODE 2: + aux residual.
template <int MODE>
__global__ __launch_bounds__(128, 2) void gemm_mma(
    const float* __restrict__ A, const float* __restrict__ Bt,
    float* __restrict__ C, const float* __restrict__ aux)
{
    extern __shared__ float sm[];
    const uint32_t sbase = smem_u32(sm);
    const int tid = threadIdx.x;
    const int wid = tid >> 5, lane = tid & 31;
    const int warpM = wid & 1, warpN = wid >> 1;      // 2 x 2 warp grid, tile 64x64
    const int grp = lane >> 2, qid = lane & 3;
    const int rowM = blockIdx.y * 128, rowN = blockIdx.x * 128;

    float acc[4][8][4];
#pragma unroll
    for (int i = 0; i < 4; i++)
#pragma unroll
        for (int j = 0; j < 8; j++)
#pragma unroll
            for (int l = 0; l < 4; l++) acc[i][j][l] = 0.0f;

    auto prefetch = [&](int kt, int slot) {
        const uint32_t sA = sbase + (uint32_t)slot * STAGE_F * 4;
        const uint32_t sB = sA + TILE_F * 4;
        const int kbase = kt * BKF;
#pragma unroll
        for (int j = 0; j < 8; j++) {
            const int t = tid + j * 128;
            const int row = t >> 3, g = t & 7;
            cp_async16(sA + (uint32_t)(row * ASTR + g * 4) * 4,
                       A + (size_t)(rowM + row) * DM + kbase + g * 4);
        }
#pragma unroll
        for (int j = 0; j < 8; j++) {
            const int t = tid + j * 128;
            const int row = t >> 3, g = t & 7;
            cp_async16(sB + (uint32_t)(row * ASTR + g * 4) * 4,
                       Bt + (size_t)(rowN + row) * DM + kbase + g * 4);
        }
        cp_commit();
    };

    prefetch(0, 0);
    prefetch(1, 1);

    for (int kt = 0; kt < KITERS; kt++) {
        if (kt < KITERS - 1) cp_wait<1>(); else cp_wait<0>();
        __syncthreads();
        if (kt + 2 < KITERS) prefetch(kt + 2, (kt + 2) % NST);

        const float* As = sm + (kt % NST) * STAGE_F;
        const float* Bs = As + TILE_F;
#pragma unroll
        for (int ks = 0; ks < 4; ks++) {
            const int c = ks * 8 + qid;
            uint32_t afr[4][4], bfr[8][2];
#pragma unroll
            for (int mt = 0; mt < 4; mt++) {
                const int r = warpM * 64 + mt * 16 + grp;
                afr[mt][0] = __float_as_uint(As[r * ASTR + c]);
                afr[mt][1] = __float_as_uint(As[(r + 8) * ASTR + c]);
                afr[mt][2] = __float_as_uint(As[r * ASTR + c + 4]);
                afr[mt][3] = __float_as_uint(As[(r + 8) * ASTR + c + 4]);
            }
#pragma unroll
            for (int nt = 0; nt < 8; nt++) {
                const int n = warpN * 64 + nt * 8 + grp;
                bfr[nt][0] = __float_as_uint(Bs[n * ASTR + c]);
                bfr[nt][1] = __float_as_uint(Bs[n * ASTR + c + 4]);
            }
#pragma unroll
            for (int mt = 0; mt < 4; mt++)
#pragma unroll
                for (int nt = 0; nt < 8; nt++)
                    mma_tf32(acc[mt][nt], afr[mt], bfr[nt]);
        }
    }

    // Epilogue
    const int bB = rowM >> 11;
#pragma unroll
    for (int mt = 0; mt < 4; mt++) {
        const int r0 = rowM + warpM * 64 + mt * 16 + grp;
        const int r1 = r0 + 8;
        const int s0 = r0 & (SS - 1), s1 = r1 & (SS - 1);
#pragma unroll
        for (int nt = 0; nt < 8; nt++) {
            const int n = rowN + warpN * 64 + nt * 8 + qid * 2;
            const float* a4 = acc[mt][nt];
            if (MODE == 0) {
                *(float2*)(C + (size_t)r0 * DM + n) = make_float2(a4[0], a4[1]);
                *(float2*)(C + (size_t)r1 * DM + n) = make_float2(a4[2], a4[3]);
            } else if (MODE == 1) {
                const int h = n >> 6, d = n & 63;
                const float2 g = *(const float2*)(aux + (size_t)bB * DM + n);
                float* base = C + (((size_t)(bB * NH + h)) << 17) + d;  // *2048*64
                *(float2*)(base + (size_t)s0 * DH) = make_float2(a4[0] * g.x, a4[1] * g.y);
                *(float2*)(base + (size_t)s1 * DH) = make_float2(a4[2] * g.x, a4[3] * g.y);
            } else {
                const float2 q0 = *(const float2*)(aux + (size_t)r0 * DM + n);
                const float2 q1 = *(const float2*)(aux + (size_t)r1 * DM + n);
                *(float2*)(C + (size_t)r0 * DM + n) = make_float2(a4[0] + q0.x, a4[1] + q0.y);
                *(float2*)(C + (size_t)r1 * DM + n) = make_float2(a4[2] + q1.x, a4[3] + q1.y);
            }
        }
    }
}

// ---------------- conversion / small kernels ----------------
__global__ __launch_bounds__(256) void conv_scale_rna(
    const float4* __restrict__ Q, const float* __restrict__ kg,
    float4* __restrict__ out)
{
    const size_t i = (size_t)blockIdx.x * 256 + threadIdx.x;
    const int c4 = (int)(i & 255);
    const int b  = (int)(i >> 19);
    const float4 g = *(const float4*)(kg + (size_t)b * DM + c4 * 4);
    float4 v = Q[i];
    v.x = rna_tf32(v.x * g.x); v.y = rna_tf32(v.y * g.y);
    v.z = rna_tf32(v.z * g.z); v.w = rna_tf32(v.w * g.w);
    out[i] = v;
}

__global__ void transpose_rna(const float* __restrict__ W, float* __restrict__ WT)
{
    __shared__ float t[32][33];
    const int x0 = blockIdx.x * 32, y0 = blockIdx.y * 32;
    const int tx = threadIdx.x, ty = threadIdx.y;  // 32 x 8
#pragma unroll
    for (int j = 0; j < 32; j += 8)
        t[ty + j][tx] = W[(size_t)(y0 + ty + j) * DM + x0 + tx];
    __syncthreads();
#pragma unroll
    for (int j = 0; j < 32; j += 8)
        WT[(size_t)(x0 + ty + j) * DM + y0 + tx] = rna_tf32(t[tx][ty + j]);
}

__global__ void transpose_w(const float* __restrict__ W, float* __restrict__ WT)
{
    int i = blockIdx.x * 256 + threadIdx.x;
    if (i < DM * NH) {
        int j = i >> 4, e = i & 15;
        WT[e * DM + j] = W[i];
    }
}

// ---------------- row_logits: smem weights + 1024 blocks ----------------
#define LROWS 16
#define LOGIT_SMEM (NH * DM * 4)   // 65536
__global__ __launch_bounds__(256) void row_logits_sm(
    const float* __restrict__ rows, const float* __restrict__ WT,
    float* __restrict__ logits, float scaleF)
{
    extern __shared__ float4 w4[];   // [16 * 256] float4
    const int tid = threadIdx.x;
    const int wid = tid >> 5, lane = tid & 31;

    const float4* wt4 = (const float4*)WT;
#pragma unroll
    for (int i = 0; i < NH; i++)
        w4[i * 256 + tid] = wt4[i * 256 + tid];
    __syncthreads();

    const float4* w0 = w4 + (size_t)wid * 256;
    const float4* w1 = w4 + (size_t)(wid + 8) * 256;
    const int rbase = blockIdx.x * LROWS;

    for (int rr = 0; rr < LROWS; rr++) {
        const int r = rbase + rr;
        const float4* rp = (const float4*)(rows + (size_t)r * DM);
        float4 v[8];
#pragma unroll
        for (int j = 0; j < 8; j++) v[j] = rp[j * 32 + lane];

        float a0 = 0.0f, a1 = 0.0f;
#pragma unroll
        for (int j = 0; j < 8; j++) {
            const float4 u0 = w0[j * 32 + lane];
            const float4 u1 = w1[j * 32 + lane];
            a0 = fmaf(v[j].x, u0.x, a0); a0 = fmaf(v[j].y, u0.y, a0);
            a0 = fmaf(v[j].z, u0.z, a0); a0 = fmaf(v[j].w, u0.w, a0);
            a1 = fmaf(v[j].x, u1.x, a1); a1 = fmaf(v[j].y, u1.y, a1);
            a1 = fmaf(v[j].z, u1.z, a1); a1 = fmaf(v[j].w, u1.w, a1);
        }
#pragma unroll
        for (int o = 16; o; o >>= 1) {
            a0 += __shfl_xor_sync(0xffffffffu, a0, o);
            a1 += __shfl_xor_sync(0xffffffffu, a1, o);
        }
        if (lane == 0) {
            const int b = r >> 11, s = r & (SS - 1);
            logits[((size_t)(b * NH + wid)) * SS + s]     = a0 * scaleF;
            logits[((size_t)(b * NH + wid + 8)) * SS + s] = a1 * scaleF;
        }
    }
}

__global__ __launch_bounds__(256) void softmax_pool(
    const float* __restrict__ logits, const float* __restrict__ src,
    size_t bStride, size_t hStride, size_t sStride,
    float* __restrict__ out)
{
    const int bh = blockIdx.x;
    const int b = bh >> 4, h = bh & 15;
    const float* lg = logits + (size_t)bh * SS;

    __shared__ float w[SS];
    __shared__ float redm[8], reds[8];
    __shared__ float4 red4[16][16];
    __shared__ float s_max, s_inv;

    const int tid = threadIdx.x;
    const int warp = tid >> 5, lane = tid & 31;

    float m = -1e30f;
    for (int s = tid; s < SS; s += 256) m = fmaxf(m, lg[s]);
#pragma unroll
    for (int o = 16; o; o >>= 1) m = fmaxf(m, __shfl_xor_sync(0xffffffffu, m, o));
    if (lane == 0) redm[warp] = m;
    __syncthreads();
    if (tid == 0) {
        float mm = redm[0];
#pragma unroll
        for (int i = 1; i < 8; i++) mm = fmaxf(mm, redm[i]);
        s_max = mm;
    }
    __syncthreads();
    const float mx = s_max;

    float sum = 0.0f;
    for (int s = tid; s < SS; s += 256) {
        const float e = __expf(lg[s] - mx);
        w[s] = e;
        sum += e;
    }
#pragma unroll
    for (int o = 16; o; o >>= 1) sum += __shfl_xor_sync(0xffffffffu, sum, o);
    if (lane == 0) reds[warp] = sum;
    __syncthreads();
    if (tid == 0) {
        float ss = 0.0f;
#pragma unroll
        for (int i = 0; i < 8; i++) ss += reds[i];
        s_inv = 1.0f / ss;
    }
    __syncthreads();
    const float inv = s_inv;

    const int d4 = tid & 15, sg = tid >> 4;
    const float* sp = src + (size_t)b * bStride + (size_t)h * hStride + d4 * 4;
    float4 acc = make_float4(0.f, 0.f, 0.f, 0.f);
    for (int s = sg; s < SS; s += 16) {
        const float4 v = *(const float4*)(sp + (size_t)s * sStride);
        const float ws = w[s];
        acc.x = fmaf(ws, v.x, acc.x); acc.y = fmaf(ws, v.y, acc.y);
        acc.z = fmaf(ws, v.z, acc.z); acc.w = fmaf(ws, v.w, acc.w);
    }
    red4[sg][d4] = acc;
    __syncthreads();
    if (sg == 0) {
        float4 t = red4[0][d4];
#pragma unroll
        for (int g = 1; g < 16; g++) {
            const float4 u = red4[g][d4];
            t.x += u.x; t.y += u.y; t.z += u.z; t.w += u.w;
        }
        *(float4*)(out + (size_t)bh * DH + d4 * 4) =
            make_float4(t.x * inv, t.y * inv, t.z * inv, t.w * inv);
    }
}

// ---------------------------------------------------------------------------
extern "C" void kernel_launch(void* const* d_in, const int* in_sizes, int n_in,
                              void* d_out, int out_size)
{
    const float* Q_seq = (const float*)d_in[0];
    const float* K_seq = (const float*)d_in[1];
    const float* WQ = (const float*)d_in[3];
    const float* WK = (const float*)d_in[4];
    const float* Wa = (const float*)d_in[5];
    const float* Wb = (const float*)d_in[6];
    const float* WP = (const float*)d_in[7];
    float* out = (float*)d_out;

    float *pAt, *pQ, *pQAK, *pWT, *pLg, *pQg, *pKg, *pWaT, *pWbT;
    cudaGetSymbolAddress((void**)&pAt,  g_At);
    cudaGetSymbolAddress((void**)&pQ,   g_Q);
    cudaGetSymbolAddress((void**)&pQAK, g_QAK);
    cudaGetSymbolAddress((void**)&pWT,  g_WT);
    cudaGetSymbolAddress((void**)&pLg,  g_logits);
    cudaGetSymbolAddress((void**)&pQg,  g_qglob);
    cudaGetSymbolAddress((void**)&pKg,  g_kglob);
    cudaGetSymbolAddress((void**)&pWaT, g_WaT);
    cudaGetSymbolAddress((void**)&pWbT, g_WbT);

    cudaFuncSetAttribute(gemm_mma<0>, cudaFuncAttributeMaxDynamicSharedMemorySize, DYN_SMEM);
    cudaFuncSetAttribute(gemm_mma<1>, cudaFuncAttributeMaxDynamicSharedMemorySize, DYN_SMEM);
    cudaFuncSetAttribute(gemm_mma<2>, cudaFuncAttributeMaxDynamicSharedMemorySize, DYN_SMEM);
    cudaFuncSetAttribute(row_logits_sm, cudaFuncAttributeMaxDynamicSharedMemorySize, LOGIT_SMEM);

    const float scaleF = 0.125f;
    const dim3 ggrid(DM / 128, MROWS / 128);     // (8, 128)
    const dim3 tgrid(32, 32), tblk(32, 8);
    const unsigned cgrid = (unsigned)(ELEMS / 4 / 256);

    transpose_w<<<(DM * NH + 255) / 256, 256>>>(Wa, pWaT);
    transpose_w<<<(DM * NH + 255) / 256, 256>>>(Wb, pWbT);

    // 1. Q = Q_seq @ WQ  (A raw fp32 -> HW tf32 truncation; B RNA-rounded)
    transpose_rna<<<tgrid, tblk>>>(WQ, pWT);
    gemm_mma<0><<<ggrid, 128, DYN_SMEM>>>(Q_seq, pWT, pQ, nullptr);

    // 2. alpha = softmax(Q @ Wa * scale); q_glob = pool(alpha, Qh)
    row_logits_sm<<<MROWS / LROWS, 256, LOGIT_SMEM>>>(pQ, pWaT, pLg, scaleF);
    softmax_pool<<<NB * NH, 256>>>(pLg, pQ,
                                   (size_t)SS * DM, (size_t)DH, (size_t)DM, pQg);

    // 3. QAK = (K_seq @ WK) * q_glob, scattered to [b,h,s,dh]
    transpose_rna<<<tgrid, tblk>>>(WK, pWT);
    gemm_mma<1><<<ggrid, 128, DYN_SMEM>>>(K_seq, pWT, pQAK, pQg);

    // 4. beta = softmax(QAK_D @ Wb * scale); k_glob = pool(beta, QAK)
    row_logits_sm<<<MROWS / LROWS, 256, LOGIT_SMEM>>>(pQAK, pWbT, pLg, scaleF);
    softmax_pool<<<NB * NH, 256>>>(pLg, pQAK,
                                   (size_t)NH * SS * DH, (size_t)SS * DH, (size_t)DH, pKg);

    // 5. out = (Q * k_glob) @ WP + Q  (A scaled+RNA-rounded by conv kernel)
    conv_scale_rna<<<cgrid, 256>>>((const float4*)pQ, pKg, (float4*)pAt);
    transpose_rna<<<tgrid, tblk>>>(WP, pWT);
    gemm_mma<2><<<ggrid, 128, DYN_SMEM>>>(pAt, pWT, out, pQ);
}

// round 13
// speedup vs baseline: 1.6455x; 1.0598x over previous
#include <cuda_runtime.h>
#include <cstdint>
#include <math.h>

#define NB 8
#define SS 2048
#define DM 1024
#define NH 16
#define DH 64
#define MROWS (NB * SS)
#define ELEMS ((size_t)MROWS * DM)

__device__ float g_At[ELEMS];            // scaled+rounded A for GEMM3 only
__device__ float g_Q[ELEMS];             // Q = Q_seq @ WQ (fp32)
__device__ float g_QAK[ELEMS];           // QAK [b,h,s,dh]
__device__ float g_WT[DM * DM];          // transposed tf32 weight (reused 3x)
__device__ float g_logits[NB * NH * SS];
__device__ float g_qglob[NB * DM];
__device__ float g_kglob[NB * DM];
__device__ float g_WaT[NH * DM];
__device__ float g_WbT[NH * DM];
__device__ float g_smx[NB * NH];         // softmax max per (b,h)
__device__ float g_sinv[NB * NH];        // softmax 1/sum per (b,h)
__device__ float g_part[NB * NH * 8 * DH]; // pooling partials [bh][chunk][64]

// ---------------- helpers ----------------
__device__ __forceinline__ uint32_t smem_u32(const void* p) {
    uint32_t a;
    asm("{ .reg .u64 t; cvta.to.shared.u64 t, %1; cvt.u32.u64 %0, t; }" : "=r"(a) : "l"(p));
    return a;
}
__device__ __forceinline__ void cp_async16(uint32_t s, const void* g) {
    asm volatile("cp.async.cg.shared.global [%0], [%1], 16;" :: "r"(s), "l"(g));
}
__device__ __forceinline__ void cp_commit() { asm volatile("cp.async.commit_group;" ::: "memory"); }
template <int N> __device__ __forceinline__ void cp_wait() {
    asm volatile("cp.async.wait_group %0;" :: "n"(N) : "memory");
}
__device__ __forceinline__ float rna_tf32(float x) {
    float r;
    asm("cvt.rna.tf32.f32 %0, %1;" : "=f"(r) : "f"(x));
    return r;
}
__device__ __forceinline__ void mma_tf32(float* c, const uint32_t* a, const uint32_t* b) {
    asm volatile(
        "mma.sync.aligned.m16n8k8.row.col.f32.tf32.tf32.f32 "
        "{%0,%1,%2,%3}, {%4,%5,%6,%7}, {%8,%9}, {%0,%1,%2,%3};"
        : "+f"(c[0]), "+f"(c[1]), "+f"(c[2]), "+f"(c[3])
        : "r"(a[0]), "r"(a[1]), "r"(a[2]), "r"(a[3]), "r"(b[0]), "r"(b[1]));
}

// ---------------- mma.sync tf32 GEMM: 128 threads, warp tile 64x64 (R12 verbatim) ----------------
#define BKF 32
#define ASTR 36
#define TILE_F (128 * ASTR)
#define STAGE_F (2 * TILE_F)
#define NST 3
#define KITERS (DM / BKF)
#define DYN_SMEM (NST * STAGE_F * 4)

// MODE 0: plain store. MODE 1: scale by aux[b,n], scatter to [b,h,s,dh]. MODE 2: + aux residual.
template <int MODE>
__global__ __launch_bounds__(128, 2) void gemm_mma(
    const float* __restrict__ A, const float* __restrict__ Bt,
    float* __restrict__ C, const float* __restrict__ aux)
{
    extern __shared__ float sm[];
    const uint32_t sbase = smem_u32(sm);
    const int tid = threadIdx.x;
    const int wid = tid >> 5, lane = tid & 31;
    const int warpM = wid & 1, warpN = wid >> 1;      // 2 x 2 warp grid, tile 64x64
    const int grp = lane >> 2, qid = lane & 3;
    const int rowM = blockIdx.y * 128, rowN = blockIdx.x * 128;

    float acc[4][8][4];
#pragma unroll
    for (int i = 0; i < 4; i++)
#pragma unroll
        for (int j = 0; j < 8; j++)
#pragma unroll
            for (int l = 0; l < 4; l++) acc[i][j][l] = 0.0f;

    auto prefetch = [&](int kt, int slot) {
        const uint32_t sA = sbase + (uint32_t)slot * STAGE_F * 4;
        const uint32_t sB = sA + TILE_F * 4;
        const int kbase = kt * BKF;
#pragma unroll
        for (int j = 0; j < 8; j++) {
            const int t = tid + j * 128;
            const int row = t >> 3, g = t & 7;
            cp_async16(sA + (uint32_t)(row * ASTR + g * 4) * 4,
                       A + (size_t)(rowM + row) * DM + kbase + g * 4);
        }
#pragma unroll
        for (int j = 0; j < 8; j++) {
            const int t = tid + j * 128;
            const int row = t >> 3, g = t & 7;
            cp_async16(sB + (uint32_t)(row * ASTR + g * 4) * 4,
                       Bt + (size_t)(rowN + row) * DM + kbase + g * 4);
        }
        cp_commit();
    };

    prefetch(0, 0);
    prefetch(1, 1);

    for (int kt = 0; kt < KITERS; kt++) {
        if (kt < KITERS - 1) cp_wait<1>(); else cp_wait<0>();
        __syncthreads();
        if (kt + 2 < KITERS) prefetch(kt + 2, (kt + 2) % NST);

        const float* As = sm + (kt % NST) * STAGE_F;
        const float* Bs = As + TILE_F;
#pragma unroll
        for (int ks = 0; ks < 4; ks++) {
            const int c = ks * 8 + qid;
            uint32_t afr[4][4], bfr[8][2];
#pragma unroll
            for (int mt = 0; mt < 4; mt++) {
                const int r = warpM * 64 + mt * 16 + grp;
                afr[mt][0] = __float_as_uint(As[r * ASTR + c]);
                afr[mt][1] = __float_as_uint(As[(r + 8) * ASTR + c]);
                afr[mt][2] = __float_as_uint(As[r * ASTR + c + 4]);
                afr[mt][3] = __float_as_uint(As[(r + 8) * ASTR + c + 4]);
            }
#pragma unroll
            for (int nt = 0; nt < 8; nt++) {
                const int n = warpN * 64 + nt * 8 + grp;
                bfr[nt][0] = __float_as_uint(Bs[n * ASTR + c]);
                bfr[nt][1] = __float_as_uint(Bs[n * ASTR + c + 4]);
            }
#pragma unroll
            for (int mt = 0; mt < 4; mt++)
#pragma unroll
                for (int nt = 0; nt < 8; nt++)
                    mma_tf32(acc[mt][nt], afr[mt], bfr[nt]);
        }
    }

    // Epilogue
    const int bB = rowM >> 11;
#pragma unroll
    for (int mt = 0; mt < 4; mt++) {
        const int r0 = rowM + warpM * 64 + mt * 16 + grp;
        const int r1 = r0 + 8;
        const int s0 = r0 & (SS - 1), s1 = r1 & (SS - 1);
#pragma unroll
        for (int nt = 0; nt < 8; nt++) {
            const int n = rowN + warpN * 64 + nt * 8 + qid * 2;
            const float* a4 = acc[mt][nt];
            if (MODE == 0) {
                *(float2*)(C + (size_t)r0 * DM + n) = make_float2(a4[0], a4[1]);
                *(float2*)(C + (size_t)r1 * DM + n) = make_float2(a4[2], a4[3]);
            } else if (MODE == 1) {
                const int h = n >> 6, d = n & 63;
                const float2 g = *(const float2*)(aux + (size_t)bB * DM + n);
                float* base = C + (((size_t)(bB * NH + h)) << 17) + d;  // *2048*64
                *(float2*)(base + (size_t)s0 * DH) = make_float2(a4[0] * g.x, a4[1] * g.y);
                *(float2*)(base + (size_t)s1 * DH) = make_float2(a4[2] * g.x, a4[3] * g.y);
            } else {
                const float2 q0 = *(const float2*)(aux + (size_t)r0 * DM + n);
                const float2 q1 = *(const float2*)(aux + (size_t)r1 * DM + n);
                *(float2*)(C + (size_t)r0 * DM + n) = make_float2(a4[0] + q0.x, a4[1] + q0.y);
                *(float2*)(C + (size_t)r1 * DM + n) = make_float2(a4[2] + q1.x, a4[3] + q1.y);
            }
        }
    }
}

// ---------------- conversion / small kernels ----------------
__global__ __launch_bounds__(256) void conv_scale_rna(
    const float4* __restrict__ Q, const float* __restrict__ kg,
    float4* __restrict__ out)
{
    const size_t i = (size_t)blockIdx.x * 256 + threadIdx.x;
    const int c4 = (int)(i & 255);
    const int b  = (int)(i >> 19);
    const float4 g = *(const float4*)(kg + (size_t)b * DM + c4 * 4);
    float4 v = Q[i];
    v.x = rna_tf32(v.x * g.x); v.y = rna_tf32(v.y * g.y);
    v.z = rna_tf32(v.z * g.z); v.w = rna_tf32(v.w * g.w);
    out[i] = v;
}

__global__ void transpose_rna(const float* __restrict__ W, float* __restrict__ WT)
{
    __shared__ float t[32][33];
    const int x0 = blockIdx.x * 32, y0 = blockIdx.y * 32;
    const int tx = threadIdx.x, ty = threadIdx.y;  // 32 x 8
#pragma unroll
    for (int j = 0; j < 32; j += 8)
        t[ty + j][tx] = W[(size_t)(y0 + ty + j) * DM + x0 + tx];
    __syncthreads();
#pragma unroll
    for (int j = 0; j < 32; j += 8)
        WT[(size_t)(x0 + ty + j) * DM + y0 + tx] = rna_tf32(t[tx][ty + j]);
}

__global__ void transpose_w(const float* __restrict__ W, float* __restrict__ WT)
{
    int i = blockIdx.x * 256 + threadIdx.x;
    if (i < DM * NH) {
        int j = i >> 4, e = i & 15;
        WT[e * DM + j] = W[i];
    }
}

// ---------------- row_logits: smem weights + 1024 blocks ----------------
#define LROWS 16
#define LOGIT_SMEM (NH * DM * 4)   // 65536
__global__ __launch_bounds__(256) void row_logits_sm(
    const float* __restrict__ rows, const float* __restrict__ WT,
    float* __restrict__ logits, float scaleF)
{
    extern __shared__ float4 w4[];   // [16 * 256] float4
    const int tid = threadIdx.x;
    const int wid = tid >> 5, lane = tid & 31;

    const float4* wt4 = (const float4*)WT;
#pragma unroll
    for (int i = 0; i < NH; i++)
        w4[i * 256 + tid] = wt4[i * 256 + tid];
    __syncthreads();

    const float4* w0 = w4 + (size_t)wid * 256;
    const float4* w1 = w4 + (size_t)(wid + 8) * 256;
    const int rbase = blockIdx.x * LROWS;

    for (int rr = 0; rr < LROWS; rr++) {
        const int r = rbase + rr;
        const float4* rp = (const float4*)(rows + (size_t)r * DM);
        float4 v[8];
#pragma unroll
        for (int j = 0; j < 8; j++) v[j] = rp[j * 32 + lane];

        float a0 = 0.0f, a1 = 0.0f;
#pragma unroll
        for (int j = 0; j < 8; j++) {
            const float4 u0 = w0[j * 32 + lane];
            const float4 u1 = w1[j * 32 + lane];
            a0 = fmaf(v[j].x, u0.x, a0); a0 = fmaf(v[j].y, u0.y, a0);
            a0 = fmaf(v[j].z, u0.z, a0); a0 = fmaf(v[j].w, u0.w, a0);
            a1 = fmaf(v[j].x, u1.x, a1); a1 = fmaf(v[j].y, u1.y, a1);
            a1 = fmaf(v[j].z, u1.z, a1); a1 = fmaf(v[j].w, u1.w, a1);
        }
#pragma unroll
        for (int o = 16; o; o >>= 1) {
            a0 += __shfl_xor_sync(0xffffffffu, a0, o);
            a1 += __shfl_xor_sync(0xffffffffu, a1, o);
        }
        if (lane == 0) {
            const int b = r >> 11, s = r & (SS - 1);
            logits[((size_t)(b * NH + wid)) * SS + s]     = a0 * scaleF;
            logits[((size_t)(b * NH + wid + 8)) * SS + s] = a1 * scaleF;
        }
    }
}

// ---------------- softmax stats: max + 1/sum per (b,h) ----------------
__global__ __launch_bounds__(256) void softmax_stats(
    const float* __restrict__ logits, float* __restrict__ smx, float* __restrict__ sinv)
{
    const int bh = blockIdx.x;
    const float* lg = logits + (size_t)bh * SS;
    __shared__ float redm[8], reds[8];
    const int tid = threadIdx.x;
    const int warp = tid >> 5, lane = tid & 31;

    float m = -1e30f;
    for (int s = tid; s < SS; s += 256) m = fmaxf(m, lg[s]);
#pragma unroll
    for (int o = 16; o; o >>= 1) m = fmaxf(m, __shfl_xor_sync(0xffffffffu, m, o));
    if (lane == 0) redm[warp] = m;
    __syncthreads();
    float mm = redm[0];
#pragma unroll
    for (int i = 1; i < 8; i++) mm = fmaxf(mm, redm[i]);

    float sum = 0.0f;
    for (int s = tid; s < SS; s += 256) sum += __expf(lg[s] - mm);
#pragma unroll
    for (int o = 16; o; o >>= 1) sum += __shfl_xor_sync(0xffffffffu, sum, o);
    if (lane == 0) reds[warp] = sum;
    __syncthreads();
    if (tid == 0) {
        float ss = 0.0f;
#pragma unroll
        for (int i = 0; i < 8; i++) ss += reds[i];
        smx[bh] = mm;
        sinv[bh] = 1.0f / ss;
    }
}

// ---------------- pool partial: 8 s-chunks x 128 bh blocks ----------------
// partial[bh][ck][d] = sum_{s in chunk} exp(lg[s]-mx)*inv * src[base + s*sStride + d]
__global__ __launch_bounds__(256) void pool_partial(
    const float* __restrict__ logits, const float* __restrict__ src,
    const float* __restrict__ smx, const float* __restrict__ sinv,
    size_t bStride, size_t hStride, size_t sStride,
    float* __restrict__ partial)
{
    const int bid = blockIdx.x;
    const int bh = bid >> 3, ck = bid & 7;
    const int b = bh >> 4, h = bh & 15;
    const float* lg = logits + (size_t)bh * SS;
    const float mx = smx[bh], inv = sinv[bh];

    const int tid = threadIdx.x;
    const int d4 = tid & 15, sg = tid >> 4;     // 16 d-float4 x 16 s-groups
    const int s0 = ck * 256;

    __shared__ float4 red4[16][16];

    const float* sp = src + (size_t)b * bStride + (size_t)h * hStride + d4 * 4;
    float4 acc = make_float4(0.f, 0.f, 0.f, 0.f);
#pragma unroll
    for (int i = 0; i < 16; i++) {
        const int s = s0 + sg + i * 16;
        const float w = __expf(lg[s] - mx) * inv;
        const float4 v = *(const float4*)(sp + (size_t)s * sStride);
        acc.x = fmaf(w, v.x, acc.x); acc.y = fmaf(w, v.y, acc.y);
        acc.z = fmaf(w, v.z, acc.z); acc.w = fmaf(w, v.w, acc.w);
    }
    red4[sg][d4] = acc;
    __syncthreads();
    if (sg == 0) {
        float4 t = red4[0][d4];
#pragma unroll
        for (int g = 1; g < 16; g++) {
            const float4 u = red4[g][d4];
            t.x += u.x; t.y += u.y; t.z += u.z; t.w += u.w;
        }
        *(float4*)(partial + (size_t)bid * DH + d4 * 4) = t;
    }
}

// ---------------- pool reduce: sum 8 chunks ----------------
__global__ __launch_bounds__(64) void pool_reduce(
    const float* __restrict__ partial, float* __restrict__ out)
{
    const int bh = blockIdx.x, d = threadIdx.x;
    const float* p = partial + (size_t)bh * 8 * DH + d;
    float t = 0.0f;
#pragma unroll
    for (int ck = 0; ck < 8; ck++) t += p[ck * DH];
    out[(size_t)bh * DH + d] = t;
}

// ---------------------------------------------------------------------------
extern "C" void kernel_launch(void* const* d_in, const int* in_sizes, int n_in,
                              void* d_out, int out_size)
{
    const float* Q_seq = (const float*)d_in[0];
    const float* K_seq = (const float*)d_in[1];
    const float* WQ = (const float*)d_in[3];
    const float* WK = (const float*)d_in[4];
    const float* Wa = (const float*)d_in[5];
    const float* Wb = (const float*)d_in[6];
    const float* WP = (const float*)d_in[7];
    float* out = (float*)d_out;

    float *pAt, *pQ, *pQAK, *pWT, *pLg, *pQg, *pKg, *pWaT, *pWbT, *pMx, *pInv, *pPart;
    cudaGetSymbolAddress((void**)&pAt,  g_At);
    cudaGetSymbolAddress((void**)&pQ,   g_Q);
    cudaGetSymbolAddress((void**)&pQAK, g_QAK);
    cudaGetSymbolAddress((void**)&pWT,  g_WT);
    cudaGetSymbolAddress((void**)&pLg,  g_logits);
    cudaGetSymbolAddress((void**)&pQg,  g_qglob);
    cudaGetSymbolAddress((void**)&pKg,  g_kglob);
    cudaGetSymbolAddress((void**)&pWaT, g_WaT);
    cudaGetSymbolAddress((void**)&pWbT, g_WbT);
    cudaGetSymbolAddress((void**)&pMx,  g_smx);
    cudaGetSymbolAddress((void**)&pInv, g_sinv);
    cudaGetSymbolAddress((void**)&pPart, g_part);

    cudaFuncSetAttribute(gemm_mma<0>, cudaFuncAttributeMaxDynamicSharedMemorySize, DYN_SMEM);
    cudaFuncSetAttribute(gemm_mma<1>, cudaFuncAttributeMaxDynamicSharedMemorySize, DYN_SMEM);
    cudaFuncSetAttribute(gemm_mma<2>, cudaFuncAttributeMaxDynamicSharedMemorySize, DYN_SMEM);
    cudaFuncSetAttribute(row_logits_sm, cudaFuncAttributeMaxDynamicSharedMemorySize, LOGIT_SMEM);

    const float scaleF = 0.125f;
    const dim3 ggrid(DM / 128, MROWS / 128);     // (8, 128)
    const dim3 tgrid(32, 32), tblk(32, 8);
    const unsigned cgrid = (unsigned)(ELEMS / 4 / 256);

    transpose_w<<<(DM * NH + 255) / 256, 256>>>(Wa, pWaT);
    transpose_w<<<(DM * NH + 255) / 256, 256>>>(Wb, pWbT);

    // 1. Q = Q_seq @ WQ  (A raw fp32 -> HW tf32 truncation; B RNA-rounded)
    transpose_rna<<<tgrid, tblk>>>(WQ, pWT);
    gemm_mma<0><<<ggrid, 128, DYN_SMEM>>>(Q_seq, pWT, pQ, nullptr);

    // 2. alpha = softmax(Q @ Wa * scale); q_glob = pool(alpha, Qh)
    row_logits_sm<<<MROWS / LROWS, 256, LOGIT_SMEM>>>(pQ, pWaT, pLg, scaleF);
    softmax_stats<<<NB * NH, 256>>>(pLg, pMx, pInv);
    pool_partial<<<NB * NH * 8, 256>>>(pLg, pQ, pMx, pInv,
                                       (size_t)SS * DM, (size_t)DH, (size_t)DM, pPart);
    pool_reduce<<<NB * NH, 64>>>(pPart, pQg);

    // 3. QAK = (K_seq @ WK) * q_glob, scattered to [b,h,s,dh]
    transpose_rna<<<tgrid, tblk>>>(WK, pWT);
    gemm_mma<1><<<ggrid, 128, DYN_SMEM>>>(K_seq, pWT, pQAK, pQg);

    // 4. beta = softmax(QAK_D @ Wb * scale); k_glob = pool(beta, QAK)
    row_logits_sm<<<MROWS / LROWS, 256, LOGIT_SMEM>>>(pQAK, pWbT, pLg, scaleF);
    softmax_stats<<<NB * NH, 256>>>(pLg, pMx, pInv);
    pool_partial<<<NB * NH * 8, 256>>>(pLg, pQAK, pMx, pInv,
                                       (size_t)NH * SS * DH, (size_t)SS * DH, (size_t)DH, pPart);
    pool_reduce<<<NB * NH, 64>>>(pPart, pKg);

    // 5. out = (Q * k_glob) @ WP + Q  (A scaled+RNA-rounded by conv kernel)
    conv_scale_rna<<<cgrid, 256>>>((const float4*)pQ, pKg, (float4*)pAt);
    transpose_rna<<<tgrid, tblk>>>(WP, pWT);
    gemm_mma<2><<<ggrid, 128, DYN_SMEM>>>(pAt, pWT, out, pQ);
}

// round 14
// speedup vs baseline: 1.6844x; 1.0236x over previous
#include <cuda_runtime.h>
#include <cstdint>
#include <math.h>

#define NB 8
#define SS 2048
#define DM 1024
#define NH 16
#define DH 64
#define MROWS (NB * SS)
#define ELEMS ((size_t)MROWS * DM)

__device__ float g_Q[ELEMS];             // Q = Q_seq @ WQ (fp32)
__device__ float g_QAK[ELEMS];           // QAK [b,h,s,dh]
__device__ float g_WTq[DM * DM];         // rna(WQ^T)
__device__ float g_WTk[DM * DM];         // rna(WK^T)
__device__ float g_WTp[DM * DM];         // WP^T (raw)
__device__ float g_WT3[(size_t)NB * DM * DM]; // per-batch rna(kg_b * WP^T)
__device__ float g_logits[NB * NH * SS];
__device__ float g_qglob[NB * DM];
__device__ float g_kglob[NB * DM];
__device__ float g_WaT[NH * DM];
__device__ float g_WbT[NH * DM];
__device__ float g_smx[NB * NH];
__device__ float g_sinv[NB * NH];
__device__ float g_part[NB * NH * 8 * DH];

// ---------------- helpers ----------------
__device__ __forceinline__ uint32_t smem_u32(const void* p) {
    uint32_t a;
    asm("{ .reg .u64 t; cvta.to.shared.u64 t, %1; cvt.u32.u64 %0, t; }" : "=r"(a) : "l"(p));
    return a;
}
__device__ __forceinline__ void cp_async16(uint32_t s, const void* g) {
    asm volatile("cp.async.cg.shared.global [%0], [%1], 16;" :: "r"(s), "l"(g));
}
__device__ __forceinline__ void cp_commit() { asm volatile("cp.async.commit_group;" ::: "memory"); }
template <int N> __device__ __forceinline__ void cp_wait() {
    asm volatile("cp.async.wait_group %0;" :: "n"(N) : "memory");
}
__device__ __forceinline__ float rna_tf32(float x) {
    float r;
    asm("cvt.rna.tf32.f32 %0, %1;" : "=f"(r) : "f"(x));
    return r;
}
__device__ __forceinline__ void mma_tf32(float* c, const uint32_t* a, const uint32_t* b) {
    asm volatile(
        "mma.sync.aligned.m16n8k8.row.col.f32.tf32.tf32.f32 "
        "{%0,%1,%2,%3}, {%4,%5,%6,%7}, {%8,%9}, {%0,%1,%2,%3};"
        : "+f"(c[0]), "+f"(c[1]), "+f"(c[2]), "+f"(c[3])
        : "r"(a[0]), "r"(a[1]), "r"(a[2]), "r"(a[3]), "r"(b[0]), "r"(b[1]));
}

// ---------------- mma.sync tf32 GEMM: 128 threads, warp tile 64x64 ----------------
// C[M,N] = A[M,K] @ Bt[N,K]^T ; M=16384, N=1024, K=1024.
// BM=BN=128, BK=32, 4 warps (2x2), 3-stage cp.async ring, 2 CTAs/SM.
// A may be raw fp32 (HW truncates to tf32); B must be pre-rounded.
#define BKF 32
#define ASTR 36
#define TILE_F (128 * ASTR)
#define STAGE_F (2 * TILE_F)
#define NST 3
#define KITERS (DM / BKF)
#define DYN_SMEM (NST * STAGE_F * 4)

// MODE 0: plain store. MODE 1: scale by aux[b,n], scatter to [b,h,s,dh].
// MODE 2: + aux residual, B selected per batch (Bt + b*DM*DM).
template <int MODE>
__global__ __launch_bounds__(128, 2) void gemm_mma(
    const float* __restrict__ A, const float* __restrict__ Bt_in,
    float* __restrict__ C, const float* __restrict__ aux)
{
    extern __shared__ float sm[];
    const uint32_t sbase = smem_u32(sm);
    const int tid = threadIdx.x;
    const int wid = tid >> 5, lane = tid & 31;
    const int warpM = wid & 1, warpN = wid >> 1;      // 2 x 2 warp grid, tile 64x64
    const int grp = lane >> 2, qid = lane & 3;
    const int rowM = blockIdx.y * 128, rowN = blockIdx.x * 128;
    const int bB = rowM >> 11;
    const float* Bt = (MODE == 2) ? Bt_in + (size_t)bB * DM * DM : Bt_in;

    float acc[4][8][4];
#pragma unroll
    for (int i = 0; i < 4; i++)
#pragma unroll
        for (int j = 0; j < 8; j++)
#pragma unroll
            for (int l = 0; l < 4; l++) acc[i][j][l] = 0.0f;

    auto prefetch = [&](int kt, int slot) {
        const uint32_t sA = sbase + (uint32_t)slot * STAGE_F * 4;
        const uint32_t sB = sA + TILE_F * 4;
        const int kbase = kt * BKF;
#pragma unroll
        for (int j = 0; j < 8; j++) {
            const int t = tid + j * 128;
            const int row = t >> 3, g = t & 7;
            cp_async16(sA + (uint32_t)(row * ASTR + g * 4) * 4,
                       A + (size_t)(rowM + row) * DM + kbase + g * 4);
        }
#pragma unroll
        for (int j = 0; j < 8; j++) {
            const int t = tid + j * 128;
            const int row = t >> 3, g = t & 7;
            cp_async16(sB + (uint32_t)(row * ASTR + g * 4) * 4,
                       Bt + (size_t)(rowN + row) * DM + kbase + g * 4);
        }
        cp_commit();
    };

    prefetch(0, 0);
    prefetch(1, 1);

    for (int kt = 0; kt < KITERS; kt++) {
        if (kt < KITERS - 1) cp_wait<1>(); else cp_wait<0>();
        __syncthreads();
        if (kt + 2 < KITERS) prefetch(kt + 2, (kt + 2) % NST);

        const float* As = sm + (kt % NST) * STAGE_F;
        const float* Bs = As + TILE_F;
#pragma unroll
        for (int ks = 0; ks < 4; ks++) {
            const int c = ks * 8 + qid;
            uint32_t afr[4][4], bfr[8][2];
#pragma unroll
            for (int mt = 0; mt < 4; mt++) {
                const int r = warpM * 64 + mt * 16 + grp;
                afr[mt][0] = __float_as_uint(As[r * ASTR + c]);
                afr[mt][1] = __float_as_uint(As[(r + 8) * ASTR + c]);
                afr[mt][2] = __float_as_uint(As[r * ASTR + c + 4]);
                afr[mt][3] = __float_as_uint(As[(r + 8) * ASTR + c + 4]);
            }
#pragma unroll
            for (int nt = 0; nt < 8; nt++) {
                const int n = warpN * 64 + nt * 8 + grp;
                bfr[nt][0] = __float_as_uint(Bs[n * ASTR + c]);
                bfr[nt][1] = __float_as_uint(Bs[n * ASTR + c + 4]);
            }
#pragma unroll
            for (int mt = 0; mt < 4; mt++)
#pragma unroll
                for (int nt = 0; nt < 8; nt++)
                    mma_tf32(acc[mt][nt], afr[mt], bfr[nt]);
        }
    }

    // Epilogue
#pragma unroll
    for (int mt = 0; mt < 4; mt++) {
        const int r0 = rowM + warpM * 64 + mt * 16 + grp;
        const int r1 = r0 + 8;
        const int s0 = r0 & (SS - 1), s1 = r1 & (SS - 1);
#pragma unroll
        for (int nt = 0; nt < 8; nt++) {
            const int n = rowN + warpN * 64 + nt * 8 + qid * 2;
            const float* a4 = acc[mt][nt];
            if (MODE == 0) {
                *(float2*)(C + (size_t)r0 * DM + n) = make_float2(a4[0], a4[1]);
                *(float2*)(C + (size_t)r1 * DM + n) = make_float2(a4[2], a4[3]);
            } else if (MODE == 1) {
                const int h = n >> 6, d = n & 63;
                const float2 g = *(const float2*)(aux + (size_t)bB * DM + n);
                float* base = C + (((size_t)(bB * NH + h)) << 17) + d;  // *2048*64
                *(float2*)(base + (size_t)s0 * DH) = make_float2(a4[0] * g.x, a4[1] * g.y);
                *(float2*)(base + (size_t)s1 * DH) = make_float2(a4[2] * g.x, a4[3] * g.y);
            } else {
                const float2 q0 = *(const float2*)(aux + (size_t)r0 * DM + n);
                const float2 q1 = *(const float2*)(aux + (size_t)r1 * DM + n);
                *(float2*)(C + (size_t)r0 * DM + n) = make_float2(a4[0] + q0.x, a4[1] + q0.y);
                *(float2*)(C + (size_t)r1 * DM + n) = make_float2(a4[2] + q1.x, a4[3] + q1.y);
            }
        }
    }
}

// ---------------- small kernels ----------------
// transpose, optionally applying rna rounding
template <bool RNA>
__global__ void transpose_k(const float* __restrict__ W, float* __restrict__ WT)
{
    __shared__ float t[32][33];
    const int x0 = blockIdx.x * 32, y0 = blockIdx.y * 32;
    const int tx = threadIdx.x, ty = threadIdx.y;  // 32 x 8
#pragma unroll
    for (int j = 0; j < 32; j += 8)
        t[ty + j][tx] = W[(size_t)(y0 + ty + j) * DM + x0 + tx];
    __syncthreads();
#pragma unroll
    for (int j = 0; j < 32; j += 8) {
        float v = t[tx][ty + j];
        WT[(size_t)(x0 + ty + j) * DM + y0 + tx] = RNA ? rna_tf32(v) : v;
    }
}

__global__ void transpose_w(const float* __restrict__ W, float* __restrict__ WT)
{
    int i = blockIdx.x * 256 + threadIdx.x;
    if (i < DM * NH) {
        int j = i >> 4, e = i & 15;
        WT[e * DM + j] = W[i];
    }
}

// WT3[b][n][k] = rna( WTp[n][k] * kg[b][k] )   (float4 over k)
__global__ __launch_bounds__(256) void scale_wt8(
    const float4* __restrict__ WTp, const float* __restrict__ kg,
    float4* __restrict__ WT3)
{
    const size_t i = (size_t)blockIdx.x * 256 + threadIdx.x;  // 2M float4
    const int k4 = (int)(i & 255);
    const int b  = (int)(i >> 18);
    const float4 w = WTp[i & ((1u << 18) - 1)];
    const float4 g = *(const float4*)(kg + (size_t)b * DM + k4 * 4);
    float4 o;
    o.x = rna_tf32(w.x * g.x); o.y = rna_tf32(w.y * g.y);
    o.z = rna_tf32(w.z * g.z); o.w = rna_tf32(w.w * g.w);
    WT3[i] = o;
}

// ---------------- row_logits: smem weights + 1024 blocks ----------------
#define LROWS 16
#define LOGIT_SMEM (NH * DM * 4)   // 65536
__global__ __launch_bounds__(256) void row_logits_sm(
    const float* __restrict__ rows, const float* __restrict__ WT,
    float* __restrict__ logits, float scaleF)
{
    extern __shared__ float4 w4[];   // [16 * 256] float4
    const int tid = threadIdx.x;
    const int wid = tid >> 5, lane = tid & 31;

    const float4* wt4 = (const float4*)WT;
#pragma unroll
    for (int i = 0; i < NH; i++)
        w4[i * 256 + tid] = wt4[i * 256 + tid];
    __syncthreads();

    const float4* w0 = w4 + (size_t)wid * 256;
    const float4* w1 = w4 + (size_t)(wid + 8) * 256;
    const int rbase = blockIdx.x * LROWS;

    for (int rr = 0; rr < LROWS; rr++) {
        const int r = rbase + rr;
        const float4* rp = (const float4*)(rows + (size_t)r * DM);
        float4 v[8];
#pragma unroll
        for (int j = 0; j < 8; j++) v[j] = rp[j * 32 + lane];

        float a0 = 0.0f, a1 = 0.0f;
#pragma unroll
        for (int j = 0; j < 8; j++) {
            const float4 u0 = w0[j * 32 + lane];
            const float4 u1 = w1[j * 32 + lane];
            a0 = fmaf(v[j].x, u0.x, a0); a0 = fmaf(v[j].y, u0.y, a0);
            a0 = fmaf(v[j].z, u0.z, a0); a0 = fmaf(v[j].w, u0.w, a0);
            a1 = fmaf(v[j].x, u1.x, a1); a1 = fmaf(v[j].y, u1.y, a1);
            a1 = fmaf(v[j].z, u1.z, a1); a1 = fmaf(v[j].w, u1.w, a1);
        }
#pragma unroll
        for (int o = 16; o; o >>= 1) {
            a0 += __shfl_xor_sync(0xffffffffu, a0, o);
            a1 += __shfl_xor_sync(0xffffffffu, a1, o);
        }
        if (lane == 0) {
            const int b = r >> 11, s = r & (SS - 1);
            logits[((size_t)(b * NH + wid)) * SS + s]     = a0 * scaleF;
            logits[((size_t)(b * NH + wid + 8)) * SS + s] = a1 * scaleF;
        }
    }
}

// ---------------- softmax stats: max + 1/sum per (b,h) ----------------
__global__ __launch_bounds__(256) void softmax_stats(
    const float* __restrict__ logits, float* __restrict__ smx, float* __restrict__ sinv)
{
    const int bh = blockIdx.x;
    const float* lg = logits + (size_t)bh * SS;
    __shared__ float redm[8], reds[8];
    const int tid = threadIdx.x;
    const int warp = tid >> 5, lane = tid & 31;

    float m = -1e30f;
    for (int s = tid; s < SS; s += 256) m = fmaxf(m, lg[s]);
#pragma unroll
    for (int o = 16; o; o >>= 1) m = fmaxf(m, __shfl_xor_sync(0xffffffffu, m, o));
    if (lane == 0) redm[warp] = m;
    __syncthreads();
    float mm = redm[0];
#pragma unroll
    for (int i = 1; i < 8; i++) mm = fmaxf(mm, redm[i]);

    float sum = 0.0f;
    for (int s = tid; s < SS; s += 256) sum += __expf(lg[s] - mm);
#pragma unroll
    for (int o = 16; o; o >>= 1) sum += __shfl_xor_sync(0xffffffffu, sum, o);
    if (lane == 0) reds[warp] = sum;
    __syncthreads();
    if (tid == 0) {
        float ss = 0.0f;
#pragma unroll
        for (int i = 0; i < 8; i++) ss += reds[i];
        smx[bh] = mm;
        sinv[bh] = 1.0f / ss;
    }
}

// ---------------- pool partial: 8 s-chunks x 128 bh blocks ----------------
__global__ __launch_bounds__(256) void pool_partial(
    const float* __restrict__ logits, const float* __restrict__ src,
    const float* __restrict__ smx, const float* __restrict__ sinv,
    size_t bStride, size_t hStride, size_t sStride,
    float* __restrict__ partial)
{
    const int bid = blockIdx.x;
    const int bh = bid >> 3, ck = bid & 7;
    const int b = bh >> 4, h = bh & 15;
    const float* lg = logits + (size_t)bh * SS;
    const float mx = smx[bh], inv = sinv[bh];

    const int tid = threadIdx.x;
    const int d4 = tid & 15, sg = tid >> 4;     // 16 d-float4 x 16 s-groups
    const int s0 = ck * 256;

    __shared__ float4 red4[16][16];

    const float* sp = src + (size_t)b * bStride + (size_t)h * hStride + d4 * 4;
    float4 acc = make_float4(0.f, 0.f, 0.f, 0.f);
#pragma unroll
    for (int i = 0; i < 16; i++) {
        const int s = s0 + sg + i * 16;
        const float w = __expf(lg[s] - mx) * inv;
        const float4 v = *(const float4*)(sp + (size_t)s * sStride);
        acc.x = fmaf(w, v.x, acc.x); acc.y = fmaf(w, v.y, acc.y);
        acc.z = fmaf(w, v.z, acc.z); acc.w = fmaf(w, v.w, acc.w);
    }
    red4[sg][d4] = acc;
    __syncthreads();
    if (sg == 0) {
        float4 t = red4[0][d4];
#pragma unroll
        for (int g = 1; g < 16; g++) {
            const float4 u = red4[g][d4];
            t.x += u.x; t.y += u.y; t.z += u.z; t.w += u.w;
        }
        *(float4*)(partial + (size_t)bid * DH + d4 * 4) = t;
    }
}

// ---------------- pool reduce: sum 8 chunks ----------------
__global__ __launch_bounds__(64) void pool_reduce(
    const float* __restrict__ partial, float* __restrict__ out)
{
    const int bh = blockIdx.x, d = threadIdx.x;
    const float* p = partial + (size_t)bh * 8 * DH + d;
    float t = 0.0f;
#pragma unroll
    for (int ck = 0; ck < 8; ck++) t += p[ck * DH];
    out[(size_t)bh * DH + d] = t;
}

// ---------------------------------------------------------------------------
extern "C" void kernel_launch(void* const* d_in, const int* in_sizes, int n_in,
                              void* d_out, int out_size)
{
    const float* Q_seq = (const float*)d_in[0];
    const float* K_seq = (const float*)d_in[1];
    const float* WQ = (const float*)d_in[3];
    const float* WK = (const float*)d_in[4];
    const float* Wa = (const float*)d_in[5];
    const float* Wb = (const float*)d_in[6];
    const float* WP = (const float*)d_in[7];
    float* out = (float*)d_out;

    float *pQ, *pQAK, *pWTq, *pWTk, *pWTp, *pWT3, *pLg, *pQg, *pKg;
    float *pWaT, *pWbT, *pMx, *pInv, *pPart;
    cudaGetSymbolAddress((void**)&pQ,   g_Q);
    cudaGetSymbolAddress((void**)&pQAK, g_QAK);
    cudaGetSymbolAddress((void**)&pWTq, g_WTq);
    cudaGetSymbolAddress((void**)&pWTk, g_WTk);
    cudaGetSymbolAddress((void**)&pWTp, g_WTp);
    cudaGetSymbolAddress((void**)&pWT3, g_WT3);
    cudaGetSymbolAddress((void**)&pLg,  g_logits);
    cudaGetSymbolAddress((void**)&pQg,  g_qglob);
    cudaGetSymbolAddress((void**)&pKg,  g_kglob);
    cudaGetSymbolAddress((void**)&pWaT, g_WaT);
    cudaGetSymbolAddress((void**)&pWbT, g_WbT);
    cudaGetSymbolAddress((void**)&pMx,  g_smx);
    cudaGetSymbolAddress((void**)&pInv, g_sinv);
    cudaGetSymbolAddress((void**)&pPart, g_part);

    cudaFuncSetAttribute(gemm_mma<0>, cudaFuncAttributeMaxDynamicSharedMemorySize, DYN_SMEM);
    cudaFuncSetAttribute(gemm_mma<1>, cudaFuncAttributeMaxDynamicSharedMemorySize, DYN_SMEM);
    cudaFuncSetAttribute(gemm_mma<2>, cudaFuncAttributeMaxDynamicSharedMemorySize, DYN_SMEM);
    cudaFuncSetAttribute(row_logits_sm, cudaFuncAttributeMaxDynamicSharedMemorySize, LOGIT_SMEM);

    const float scaleF = 0.125f;
    const dim3 ggrid(DM / 128, MROWS / 128);     // (8, 128)
    const dim3 tgrid(32, 32), tblk(32, 8);

    // 0. all weight prep upfront
    transpose_w<<<(DM * NH + 255) / 256, 256>>>(Wa, pWaT);
    transpose_w<<<(DM * NH + 255) / 256, 256>>>(Wb, pWbT);
    transpose_k<true><<<tgrid, tblk>>>(WQ, pWTq);
    transpose_k<true><<<tgrid, tblk>>>(WK, pWTk);
    transpose_k<false><<<tgrid, tblk>>>(WP, pWTp);

    // 1. Q = Q_seq @ WQ  (A raw fp32 -> HW tf32 truncation; B RNA-rounded)
    gemm_mma<0><<<ggrid, 128, DYN_SMEM>>>(Q_seq, pWTq, pQ, nullptr);

    // 2. alpha = softmax(Q @ Wa * scale); q_glob = pool(alpha, Qh)
    row_logits_sm<<<MROWS / LROWS, 256, LOGIT_SMEM>>>(pQ, pWaT, pLg, scaleF);
    softmax_stats<<<NB * NH, 256>>>(pLg, pMx, pInv);
    pool_partial<<<NB * NH * 8, 256>>>(pLg, pQ, pMx, pInv,
                                       (size_t)SS * DM, (size_t)DH, (size_t)DM, pPart);
    pool_reduce<<<NB * NH, 64>>>(pPart, pQg);

    // 3. QAK = (K_seq @ WK) * q_glob, scattered to [b,h,s,dh]
    gemm_mma<1><<<ggrid, 128, DYN_SMEM>>>(K_seq, pWTk, pQAK, pQg);

    // 4. beta = softmax(QAK_D @ Wb * scale); k_glob = pool(beta, QAK)
    row_logits_sm<<<MROWS / LROWS, 256, LOGIT_SMEM>>>(pQAK, pWbT, pLg, scaleF);
    softmax_stats<<<NB * NH, 256>>>(pLg, pMx, pInv);
    pool_partial<<<NB * NH * 8, 256>>>(pLg, pQAK, pMx, pInv,
                                       (size_t)NH * SS * DH, (size_t)SS * DH, (size_t)DH, pPart);
    pool_reduce<<<NB * NH, 64>>>(pPart, pKg);

    // 5. out = Q @ (diag(kg_b) WP) + Q  (scale folded into per-batch B)
    scale_wt8<<<(unsigned)((size_t)NB * DM * DM / 4 / 256), 256>>>(
        (const float4*)pWTp, pKg, (float4*)pWT3);
    gemm_mma<2><<<ggrid, 128, DYN_SMEM>>>(pQ, pWT3, out, pQ);
}